// round 14
// baseline (speedup 1.0000x reference)
#include <cuda_runtime.h>
#include <cuda.h>
#include <cuda_fp16.h>
#include <cuda_bf16.h>
#include <cstdint>
#include <cstdio>

// ============================================================================
// Problem: x [2,4096,4096] f32, w [16384,4096] f32 -> out [2,4096,16384] f32
// out = x @ w_q^T,  w_q = clip(round(w / mean|w|), -1, 1)   (x-scaling cancels)
// ============================================================================
static constexpr int M_TOT = 8192;
static constexpr int N_TOT = 16384;
static constexpr int K_TOT = 4096;

// GEMM tiling (legacy HMMA path: mma.sync.m16n8k16)
static constexpr int BM = 128;
static constexpr int BN = 128;
static constexpr int BK = 64;                       // 128 bytes/row fp16 (SW128 atom)
static constexpr int STAGES = 6;
static constexpr int K_ITERS = K_TOT / BK;          // 64
static constexpr int A_BYTES = BM * BK * 2;         // 16384
static constexpr int B_BYTES = BN * BK * 2;         // 16384
static constexpr int NWARPS_COMPUTE = 8;            // 2 (M) x 4 (N), warp tile 64x32
static constexpr int NTHREADS = (NWARPS_COMPUTE + 1) * 32;  // +1 producer warp

// SMEM layout (dynamic)
static constexpr int SM_BAR = 0;                    // full[s]=s*16, empty[s]=s*16+8
static constexpr int SM_A = 1024;
static constexpr int SM_B = SM_A + STAGES * A_BYTES;
static constexpr int SMEM_TOTAL = SM_B + STAGES * B_BYTES;  // 1024 + 192 KB

// Scratch (allocation-free rule: __device__ globals)
static __device__ __half g_xq[(size_t)M_TOT * K_TOT];   // 64 MB
static __device__ __half g_wq[(size_t)N_TOT * K_TOT];   // 128 MB
static __device__ double g_partials[1024];
static __device__ float  g_wscale_f;

// ============================================================================
// PTX helpers
// ============================================================================
__device__ __forceinline__ uint32_t elect_one_pred() {
    uint32_t pred;
    asm volatile(
        "{\n\t.reg .pred p;\n\telect.sync _|p, 0xFFFFFFFF;\n\tselp.b32 %0, 1, 0, p;\n\t}"
        : "=r"(pred));
    return pred;
}
__device__ __forceinline__ uint32_t smem_to_u32(const void* p) {
    uint32_t a;
    asm("{ .reg .u64 t; cvta.to.shared.u64 t, %1; cvt.u32.u64 %0, t; }" : "=r"(a) : "l"(p));
    return a;
}

#define MBARRIER_INIT(addr, cnt) \
    asm volatile("mbarrier.init.shared.b64 [%0], %1;" :: "r"((uint32_t)(addr)), "r"((uint32_t)(cnt)) : "memory")
#define MBARRIER_EXPECT_TX(addr, bytes) \
    asm volatile("mbarrier.arrive.expect_tx.shared.b64 _, [%0], %1;" :: "r"((uint32_t)(addr)), "r"((uint32_t)(bytes)) : "memory")
#define MBARRIER_ARRIVE(addr) \
    asm volatile("mbarrier.arrive.shared.b64 _, [%0];" :: "r"((uint32_t)(addr)) : "memory")

#define MBARRIER_WAIT_PARITY(mbar, par) do {                                        \
    uint32_t _m = (uint32_t)(mbar); uint32_t _p = (uint32_t)(par);                  \
    asm volatile(                                                                   \
        "{\n\t.reg .pred P1;\n\t"                                                   \
        "WAIT_LOOP_%=:\n\t"                                                         \
        "mbarrier.try_wait.parity.acquire.cta.shared::cta.b64 P1, [%0], %1, 0x989680;\n\t" \
        "@P1 bra.uni WAIT_DONE_%=;\n\t"                                             \
        "bra.uni WAIT_LOOP_%=;\n\t"                                                 \
        "WAIT_DONE_%=:\n\t}"                                                        \
        :: "r"(_m), "r"(_p) : "memory");                                            \
} while (0)

#define MBARRIER_WAIT_PARITY_RELAXED(mbar, par) do {                                \
    uint32_t _m = (uint32_t)(mbar); uint32_t _p = (uint32_t)(par);                  \
    asm volatile(                                                                   \
        "{\n\t.reg .pred P1;\n\t"                                                   \
        "WAIT_LOOP_%=:\n\t"                                                         \
        "mbarrier.try_wait.parity.relaxed.cta.shared::cta.b64 P1, [%0], %1, 0x989680;\n\t" \
        "@P1 bra.uni WAIT_DONE_%=;\n\t"                                             \
        "bra.uni WAIT_LOOP_%=;\n\t"                                                 \
        "WAIT_DONE_%=:\n\t}"                                                        \
        :: "r"(_m), "r"(_p) : "memory");                                            \
} while (0)

#define TMA_LOAD_3D(smem_addr, tmap, cx, cy, cz, mbar)                              \
    asm volatile(                                                                   \
        "cp.async.bulk.tensor.3d.shared::cta.global.tile.mbarrier::complete_tx::bytes " \
        "[%0], [%1, {%2, %3, %4}], [%5];"                                           \
        :: "r"((uint32_t)(smem_addr)), "l"(tmap), "r"((int32_t)(cx)),               \
           "r"((int32_t)(cy)), "r"((int32_t)(cz)), "r"((uint32_t)(mbar)) : "memory")

#define LDMATRIX_X4(r0, r1, r2, r3, addr)                                           \
    asm volatile("ldmatrix.sync.aligned.m8n8.x4.shared.b16 {%0,%1,%2,%3}, [%4];"    \
                 : "=r"(r0), "=r"(r1), "=r"(r2), "=r"(r3) : "r"(addr))

#define MMA_16816(d, a, b)                                                          \
    asm volatile(                                                                   \
        "mma.sync.aligned.m16n8k16.row.col.f32.f16.f16.f32 "                        \
        "{%0,%1,%2,%3}, {%4,%5,%6,%7}, {%8,%9}, {%0,%1,%2,%3};"                     \
        : "+f"((d)[0]), "+f"((d)[1]), "+f"((d)[2]), "+f"((d)[3])                    \
        : "r"((a)[0]), "r"((a)[1]), "r"((a)[2]), "r"((a)[3]),                       \
          "r"((b)[0]), "r"((b)[1]))

// SW128 swizzle (Swizzle<3,4,3>): bits[6:4] ^= bits[9:7]
__device__ __forceinline__ uint32_t swz128(uint32_t off) {
    return off ^ ((off >> 3) & 0x70);
}

// ============================================================================
// Kernel 1: abs-sum of weight in fp64 (deterministic fixed tree)
// ============================================================================
__global__ void absmean_partial_kernel(const float4* __restrict__ w) {
    __shared__ double sdata[256];
    const int tid = threadIdx.x;
    const int gid = blockIdx.x * 256 + tid;
    const int stride = 1024 * 256;
    const int n4 = (N_TOT * K_TOT) / 4;
    double s = 0.0;
    for (int i = gid; i < n4; i += stride) {
        float4 v = w[i];
        s += (double)fabsf(v.x);
        s += (double)fabsf(v.y);
        s += (double)fabsf(v.z);
        s += (double)fabsf(v.w);
    }
    sdata[tid] = s;
    __syncthreads();
    for (int off = 128; off > 0; off >>= 1) {
        if (tid < off) sdata[tid] += sdata[tid + off];
        __syncthreads();
    }
    if (tid == 0) g_partials[blockIdx.x] = sdata[0];
}

__global__ void absmean_final_kernel() {
    __shared__ double sdata[1024];
    const int tid = threadIdx.x;
    sdata[tid] = g_partials[tid];
    __syncthreads();
    for (int off = 512; off > 0; off >>= 1) {
        if (tid < off) sdata[tid] += sdata[tid + off];
        __syncthreads();
    }
    if (tid == 0) {
        double mean = sdata[0] / (double)((size_t)N_TOT * K_TOT);
        float s = (float)mean;
        if (s < 1e-5f) s = 1e-5f;
        g_wscale_f = s;
    }
}

// ============================================================================
// Kernel 2: quantize weight to ternary fp16.  q = clip(rint(w/scale), -1, 1)
// ============================================================================
__global__ void quantize_w_kernel(const float4* __restrict__ w, uint2* __restrict__ out) {
    const float s = g_wscale_f;
    const int n4 = (N_TOT * K_TOT) / 4;
    const int stride = gridDim.x * blockDim.x;
    for (int i = blockIdx.x * blockDim.x + threadIdx.x; i < n4; i += stride) {
        float4 v = w[i];
        float q0 = fminf(1.f, fmaxf(-1.f, rintf(v.x / s)));
        float q1 = fminf(1.f, fmaxf(-1.f, rintf(v.y / s)));
        float q2 = fminf(1.f, fmaxf(-1.f, rintf(v.z / s)));
        float q3 = fminf(1.f, fmaxf(-1.f, rintf(v.w / s)));
        __half2 h01 = __floats2half2_rn(q0, q1);
        __half2 h23 = __floats2half2_rn(q2, q3);
        uint2 o;
        o.x = *reinterpret_cast<uint32_t*>(&h01);
        o.y = *reinterpret_cast<uint32_t*>(&h23);
        out[i] = o;
    }
}

// ============================================================================
// Kernel 3: convert x to fp16 (per-token scaling cancels algebraically)
// ============================================================================
__global__ void quantize_x_kernel(const float4* __restrict__ x, uint2* __restrict__ out) {
    const int n4 = (M_TOT * K_TOT) / 4;
    const int stride = gridDim.x * blockDim.x;
    for (int i = blockIdx.x * blockDim.x + threadIdx.x; i < n4; i += stride) {
        float4 v = x[i];
        __half2 h01 = __floats2half2_rn(v.x, v.y);
        __half2 h23 = __floats2half2_rn(v.z, v.w);
        uint2 o;
        o.x = *reinterpret_cast<uint32_t*>(&h01);
        o.y = *reinterpret_cast<uint32_t*>(&h23);
        out[i] = o;
    }
}

// ============================================================================
// Kernel 4: f16 GEMM, mma.sync (HMMA) + TMA 6-stage mbarrier pipeline.
//   warps 0-7: compute (2x4 warp grid, 64x32 warp tile)
//   warp  8  : TMA producer
// ============================================================================
__global__ void __launch_bounds__(NTHREADS, 1) gemm_kernel(
    const __grid_constant__ CUtensorMap tma_a,
    const __grid_constant__ CUtensorMap tma_b,
    float* __restrict__ out)
{
    extern __shared__ char smem[];
    const uint32_t sb = smem_to_u32(smem);
    const int tid = threadIdx.x;
    const int wid = tid >> 5;
    const int lane = tid & 31;

    // Grouped tile order for L2 reuse. 64 M-tiles x 128 N-tiles.
    // group = 8 M-tiles x all N-tiles, n-major within group.
    const int bid = blockIdx.x;
    const int group = bid >> 10;                  // /(8*128)
    const int r = bid & 1023;
    const int bm = (group << 3) + (r & 7);
    const int bn = r >> 3;
    const int m0 = bm * BM;
    const int n0 = bn * BN;

    if (tid == 0) {
        #pragma unroll
        for (int s = 0; s < STAGES; s++) {
            MBARRIER_INIT(sb + SM_BAR + s * 16, 1);                 // full[s]: TMA tx
            MBARRIER_INIT(sb + SM_BAR + s * 16 + 8, NWARPS_COMPUTE); // empty[s]: 1/warp
        }
    }
    __syncthreads();

    if (wid == NWARPS_COMPUTE) {
        // ------------------------- TMA producer -------------------------
        if (elect_one_pred()) {
            int s = 0, phase = 1;   // fresh empty barriers: first STAGES waits pass
            for (int it = 0; it < K_ITERS; ++it) {
                MBARRIER_WAIT_PARITY_RELAXED(sb + SM_BAR + s * 16 + 8, phase);
                MBARRIER_EXPECT_TX(sb + SM_BAR + s * 16, A_BYTES + B_BYTES);
                TMA_LOAD_3D(sb + SM_A + s * A_BYTES, &tma_a, it * BK, m0, 0, sb + SM_BAR + s * 16);
                TMA_LOAD_3D(sb + SM_B + s * B_BYTES, &tma_b, it * BK, n0, 0, sb + SM_BAR + s * 16);
                if (++s == STAGES) { s = 0; phase ^= 1; }
            }
        }
        return;
    }

    // --------------------------- compute warps ---------------------------
    const int warp_m = wid >> 2;                  // 0..1 -> 64 rows
    const int warp_n = wid & 3;                   // 0..3 -> 32 cols
    float acc[4][4][4];                           // [mi][nj][4]
    #pragma unroll
    for (int i = 0; i < 4; i++)
        #pragma unroll
        for (int j = 0; j < 4; j++)
            #pragma unroll
            for (int c = 0; c < 4; c++) acc[i][j][c] = 0.f;

    // Per-thread ldmatrix byte offsets within a stage tile (before swizzle):
    // A (16x16 tile mi, kstep ks): row = warp_m*64 + mi*16 + (lane&15), kb = (lane>>4)*16
    // B (x4 covers n16 group g, kstep ks): q = lane>>3,
    //   nrow = warp_n*32 + g*16 + (q>>1)*8 + (lane&7), kb = (q&1)*16
    const uint32_t a_row = warp_m * 64 + (lane & 15);
    const uint32_t a_kb  = (lane >> 4) * 16;
    const uint32_t q     = lane >> 3;
    const uint32_t b_row = warp_n * 32 + ((q >> 1) * 8) + (lane & 7);
    const uint32_t b_kb  = (q & 1) * 16;

    int s = 0, phase = 0;
    for (int it = 0; it < K_ITERS; ++it) {
        MBARRIER_WAIT_PARITY(sb + SM_BAR + s * 16, phase);
        const uint32_t aBase = sb + SM_A + s * A_BYTES;
        const uint32_t bBase = sb + SM_B + s * B_BYTES;

        #pragma unroll
        for (int ks = 0; ks < BK / 16; ++ks) {
            uint32_t a[4][4];
            #pragma unroll
            for (int mi = 0; mi < 4; ++mi) {
                uint32_t off = (a_row + mi * 16) * 128 + ks * 32 + a_kb;
                LDMATRIX_X4(a[mi][0], a[mi][1], a[mi][2], a[mi][3], aBase + swz128(off));
            }
            uint32_t b[2][4];
            #pragma unroll
            for (int g = 0; g < 2; ++g) {
                uint32_t off = (b_row + g * 16) * 128 + ks * 32 + b_kb;
                LDMATRIX_X4(b[g][0], b[g][1], b[g][2], b[g][3], bBase + swz128(off));
            }
            #pragma unroll
            for (int mi = 0; mi < 4; ++mi) {
                #pragma unroll
                for (int nj = 0; nj < 4; ++nj) {
                    uint32_t bf[2] = { b[nj >> 1][2 * (nj & 1)], b[nj >> 1][2 * (nj & 1) + 1] };
                    MMA_16816(acc[mi][nj], a[mi], bf);
                }
            }
        }
        __syncwarp();
        if (elect_one_pred()) MBARRIER_ARRIVE(sb + SM_BAR + s * 16 + 8);
        if (++s == STAGES) { s = 0; phase ^= 1; }
    }

    // ------------------------------ epilogue ------------------------------
    // c fragment: thread holds C[m = lane/4 (+8)][n = 2*(lane%4) (+1)]
    const int er = m0 + warp_m * 64 + (lane >> 2);
    const int ec = n0 + warp_n * 32 + 2 * (lane & 3);
    #pragma unroll
    for (int mi = 0; mi < 4; ++mi) {
        #pragma unroll
        for (int nj = 0; nj < 4; ++nj) {
            float* p0 = out + (size_t)(er + mi * 16) * N_TOT + ec + nj * 8;
            float* p1 = p0 + (size_t)8 * N_TOT;
            reinterpret_cast<float2*>(p0)[0] = make_float2(acc[mi][nj][0], acc[mi][nj][1]);
            reinterpret_cast<float2*>(p1)[0] = make_float2(acc[mi][nj][2], acc[mi][nj][3]);
        }
    }
}

// ============================================================================
// Host side
// ============================================================================
typedef CUresult (*EncodeTiledFn)(
    CUtensorMap*, CUtensorMapDataType, cuuint32_t, void*,
    const cuuint64_t*, const cuuint64_t*, const cuuint32_t*, const cuuint32_t*,
    CUtensorMapInterleave, CUtensorMapSwizzle, CUtensorMapL2promotion,
    CUtensorMapFloatOOBfill);

static void make_tmap_f16_3d(EncodeTiledFn enc, CUtensorMap* tm, void* base,
                             uint64_t rows, uint32_t box_rows) {
    cuuint64_t dims[3]    = {(cuuint64_t)K_TOT, (cuuint64_t)rows, 1};
    cuuint64_t strides[2] = {(cuuint64_t)K_TOT * 2, (cuuint64_t)K_TOT * rows * 2};
    cuuint32_t box[3]     = {(cuuint32_t)BK, (cuuint32_t)box_rows, 1};
    cuuint32_t estr[3]    = {1, 1, 1};
    enc(tm, CU_TENSOR_MAP_DATA_TYPE_FLOAT16, 3, base, dims, strides, box, estr,
        CU_TENSOR_MAP_INTERLEAVE_NONE, CU_TENSOR_MAP_SWIZZLE_128B,
        CU_TENSOR_MAP_L2_PROMOTION_L2_128B, CU_TENSOR_MAP_FLOAT_OOB_FILL_NONE);
}

extern "C" void kernel_launch(void* const* d_in, const int* in_sizes, int n_in,
                              void* d_out, int out_size) {
    const float* x = (const float*)d_in[0];
    const float* w = (const float*)d_in[1];
    if (n_in >= 2 && in_sizes[0] == N_TOT * K_TOT) {  // weight first
        w = (const float*)d_in[0];
        x = (const float*)d_in[1];
    }
    float* out = (float*)d_out;

    void* xq_ptr = nullptr;
    void* wq_ptr = nullptr;
    cudaGetSymbolAddress(&xq_ptr, g_xq);
    cudaGetSymbolAddress(&wq_ptr, g_wq);

    EncodeTiledFn enc = nullptr;
    {
        void* p = nullptr;
        cudaDriverEntryPointQueryResult st;
#if CUDART_VERSION >= 12050
        cudaGetDriverEntryPointByVersion("cuTensorMapEncodeTiled", &p, 12000,
                                         cudaEnableDefault, &st);
#else
        cudaGetDriverEntryPoint("cuTensorMapEncodeTiled", &p, cudaEnableDefault, &st);
#endif
        enc = (EncodeTiledFn)p;
    }

    CUtensorMap tma_a, tma_b;
    make_tmap_f16_3d(enc, &tma_a, xq_ptr, M_TOT, BM);   // A: [K,M] K-major, box [64,128]
    make_tmap_f16_3d(enc, &tma_b, wq_ptr, N_TOT, BN);   // B: [K,N] K-major, box [64,128]

    absmean_partial_kernel<<<1024, 256>>>((const float4*)w);
    absmean_final_kernel<<<1, 1024>>>();
    quantize_w_kernel<<<16384, 256>>>((const float4*)w, (uint2*)wq_ptr);
    quantize_x_kernel<<<8192, 256>>>((const float4*)x, (uint2*)xq_ptr);

    cudaFuncSetAttribute(gemm_kernel, cudaFuncAttributeMaxDynamicSharedMemorySize, SMEM_TOTAL);
    const int grid = (M_TOT / BM) * (N_TOT / BN);   // 64 * 128 = 8192
    gemm_kernel<<<grid, NTHREADS, SMEM_TOTAL>>>(tma_a, tma_b, out);
    (void)out_size; (void)n_in;
}

// round 16
// speedup vs baseline: 1.0014x; 1.0014x over previous
#include <cuda_runtime.h>
#include <cuda.h>
#include <cuda_fp16.h>
#include <cuda_bf16.h>
#include <cstdint>
#include <cstdio>

// ============================================================================
// Problem: x [2,4096,4096] f32, w [16384,4096] f32 -> out [2,4096,16384] f32
// out = x @ w_q^T,  w_q = clip(round(w / mean|w|), -1, 1)   (x-scaling cancels)
// ============================================================================
static constexpr int M_TOT = 8192;
static constexpr int N_TOT = 16384;
static constexpr int K_TOT = 4096;

// GEMM tiling (legacy HMMA path: mma.sync.m16n8k16)
static constexpr int BM = 128;
static constexpr int BN = 128;
static constexpr int BK = 64;                       // 128 bytes/row fp16 (SW128 atom)
static constexpr int STAGES = 6;
static constexpr int K_ITERS = K_TOT / BK;          // 64
static constexpr int A_BYTES = BM * BK * 2;         // 16384
static constexpr int B_BYTES = BN * BK * 2;         // 16384
static constexpr int NWARPS_COMPUTE = 8;            // 2 (M) x 4 (N), warp tile 64x32
static constexpr int NTHREADS = (NWARPS_COMPUTE + 1) * 32;  // +1 producer warp

// SMEM layout (dynamic)
static constexpr int SM_BAR = 0;                    // full[s]=s*16, empty[s]=s*16+8
static constexpr int SM_A = 1024;
static constexpr int SM_B = SM_A + STAGES * A_BYTES;
static constexpr int SMEM_TOTAL = SM_B + STAGES * B_BYTES;  // 1024 + 192 KB

// Scratch (allocation-free rule: __device__ globals)
static __device__ __half g_xq[(size_t)M_TOT * K_TOT];   // 64 MB
static __device__ __half g_wq[(size_t)N_TOT * K_TOT];   // 128 MB
static __device__ double g_partials[1024];
static __device__ float  g_wscale_f;

// ============================================================================
// PTX helpers
// ============================================================================
__device__ __forceinline__ uint32_t elect_one_pred() {
    uint32_t pred;
    asm volatile(
        "{\n\t.reg .pred p;\n\telect.sync _|p, 0xFFFFFFFF;\n\tselp.b32 %0, 1, 0, p;\n\t}"
        : "=r"(pred));
    return pred;
}
__device__ __forceinline__ uint32_t smem_to_u32(const void* p) {
    uint32_t a;
    asm("{ .reg .u64 t; cvta.to.shared.u64 t, %1; cvt.u32.u64 %0, t; }" : "=r"(a) : "l"(p));
    return a;
}

#define MBARRIER_INIT(addr, cnt) \
    asm volatile("mbarrier.init.shared.b64 [%0], %1;" :: "r"((uint32_t)(addr)), "r"((uint32_t)(cnt)) : "memory")
#define MBARRIER_EXPECT_TX(addr, bytes) \
    asm volatile("mbarrier.arrive.expect_tx.shared.b64 _, [%0], %1;" :: "r"((uint32_t)(addr)), "r"((uint32_t)(bytes)) : "memory")
#define MBARRIER_ARRIVE(addr) \
    asm volatile("mbarrier.arrive.shared.b64 _, [%0];" :: "r"((uint32_t)(addr)) : "memory")

#define MBARRIER_WAIT_PARITY(mbar, par) do {                                        \
    uint32_t _m = (uint32_t)(mbar); uint32_t _p = (uint32_t)(par);                  \
    asm volatile(                                                                   \
        "{\n\t.reg .pred P1;\n\t"                                                   \
        "WAIT_LOOP_%=:\n\t"                                                         \
        "mbarrier.try_wait.parity.acquire.cta.shared::cta.b64 P1, [%0], %1, 0x989680;\n\t" \
        "@P1 bra.uni WAIT_DONE_%=;\n\t"                                             \
        "bra.uni WAIT_LOOP_%=;\n\t"                                                 \
        "WAIT_DONE_%=:\n\t}"                                                        \
        :: "r"(_m), "r"(_p) : "memory");                                            \
} while (0)

#define MBARRIER_WAIT_PARITY_RELAXED(mbar, par) do {                                \
    uint32_t _m = (uint32_t)(mbar); uint32_t _p = (uint32_t)(par);                  \
    asm volatile(                                                                   \
        "{\n\t.reg .pred P1;\n\t"                                                   \
        "WAIT_LOOP_%=:\n\t"                                                         \
        "mbarrier.try_wait.parity.relaxed.cta.shared::cta.b64 P1, [%0], %1, 0x989680;\n\t" \
        "@P1 bra.uni WAIT_DONE_%=;\n\t"                                             \
        "bra.uni WAIT_LOOP_%=;\n\t"                                                 \
        "WAIT_DONE_%=:\n\t}"                                                        \
        :: "r"(_m), "r"(_p) : "memory");                                            \
} while (0)

#define TMA_LOAD_3D(smem_addr, tmap, cx, cy, cz, mbar)                              \
    asm volatile(                                                                   \
        "cp.async.bulk.tensor.3d.shared::cta.global.tile.mbarrier::complete_tx::bytes " \
        "[%0], [%1, {%2, %3, %4}], [%5];"                                           \
        :: "r"((uint32_t)(smem_addr)), "l"(tmap), "r"((int32_t)(cx)),               \
           "r"((int32_t)(cy)), "r"((int32_t)(cz)), "r"((uint32_t)(mbar)) : "memory")

#define LDMATRIX_X4(r0, r1, r2, r3, addr)                                           \
    asm volatile("ldmatrix.sync.aligned.m8n8.x4.shared.b16 {%0,%1,%2,%3}, [%4];"    \
                 : "=r"(r0), "=r"(r1), "=r"(r2), "=r"(r3) : "r"(addr))

#define MMA_16816(d, a, b)                                                          \
    asm volatile(                                                                   \
        "mma.sync.aligned.m16n8k16.row.col.f32.f16.f16.f32 "                        \
        "{%0,%1,%2,%3}, {%4,%5,%6,%7}, {%8,%9}, {%0,%1,%2,%3};"                     \
        : "+f"((d)[0]), "+f"((d)[1]), "+f"((d)[2]), "+f"((d)[3])                    \
        : "r"((a)[0]), "r"((a)[1]), "r"((a)[2]), "r"((a)[3]),                       \
          "r"((b)[0]), "r"((b)[1]))

// SW128 swizzle (Swizzle<3,4,3>): bits[6:4] ^= bits[9:7]
__device__ __forceinline__ uint32_t swz128(uint32_t off) {
    return off ^ ((off >> 3) & 0x70);
}

// ============================================================================
// Kernel 1: abs-sum of weight in fp64 (deterministic fixed tree)
// ============================================================================
__global__ void absmean_partial_kernel(const float4* __restrict__ w) {
    __shared__ double sdata[256];
    const int tid = threadIdx.x;
    const int gid = blockIdx.x * 256 + tid;
    const int stride = 1024 * 256;
    const int n4 = (N_TOT * K_TOT) / 4;
    double s = 0.0;
    for (int i = gid; i < n4; i += stride) {
        float4 v = w[i];
        s += (double)fabsf(v.x);
        s += (double)fabsf(v.y);
        s += (double)fabsf(v.z);
        s += (double)fabsf(v.w);
    }
    sdata[tid] = s;
    __syncthreads();
    for (int off = 128; off > 0; off >>= 1) {
        if (tid < off) sdata[tid] += sdata[tid + off];
        __syncthreads();
    }
    if (tid == 0) g_partials[blockIdx.x] = sdata[0];
}

__global__ void absmean_final_kernel() {
    __shared__ double sdata[1024];
    const int tid = threadIdx.x;
    sdata[tid] = g_partials[tid];
    __syncthreads();
    for (int off = 512; off > 0; off >>= 1) {
        if (tid < off) sdata[tid] += sdata[tid + off];
        __syncthreads();
    }
    if (tid == 0) {
        double mean = sdata[0] / (double)((size_t)N_TOT * K_TOT);
        float s = (float)mean;
        if (s < 1e-5f) s = 1e-5f;
        g_wscale_f = s;
    }
}

// ============================================================================
// Kernel 2: quantize weight to ternary fp16.  q = clip(rint(w/scale), -1, 1)
// ============================================================================
__global__ void quantize_w_kernel(const float4* __restrict__ w, uint2* __restrict__ out) {
    const float s = g_wscale_f;
    const int n4 = (N_TOT * K_TOT) / 4;
    const int stride = gridDim.x * blockDim.x;
    for (int i = blockIdx.x * blockDim.x + threadIdx.x; i < n4; i += stride) {
        float4 v = w[i];
        float q0 = fminf(1.f, fmaxf(-1.f, rintf(v.x / s)));
        float q1 = fminf(1.f, fmaxf(-1.f, rintf(v.y / s)));
        float q2 = fminf(1.f, fmaxf(-1.f, rintf(v.z / s)));
        float q3 = fminf(1.f, fmaxf(-1.f, rintf(v.w / s)));
        __half2 h01 = __floats2half2_rn(q0, q1);
        __half2 h23 = __floats2half2_rn(q2, q3);
        uint2 o;
        o.x = *reinterpret_cast<uint32_t*>(&h01);
        o.y = *reinterpret_cast<uint32_t*>(&h23);
        out[i] = o;
    }
}

// ============================================================================
// Kernel 3: convert x to fp16 (per-token scaling cancels algebraically)
// ============================================================================
__global__ void quantize_x_kernel(const float4* __restrict__ x, uint2* __restrict__ out) {
    const int n4 = (M_TOT * K_TOT) / 4;
    const int stride = gridDim.x * blockDim.x;
    for (int i = blockIdx.x * blockDim.x + threadIdx.x; i < n4; i += stride) {
        float4 v = x[i];
        __half2 h01 = __floats2half2_rn(v.x, v.y);
        __half2 h23 = __floats2half2_rn(v.z, v.w);
        uint2 o;
        o.x = *reinterpret_cast<uint32_t*>(&h01);
        o.y = *reinterpret_cast<uint32_t*>(&h23);
        out[i] = o;
    }
}

// ============================================================================
// Kernel 4: f16 GEMM, mma.sync (HMMA) + TMA 6-stage mbarrier pipeline.
//   warps 0-7: compute (2x4 warp grid, 64x32 warp tile)
//   warp  8  : TMA producer
// ============================================================================
__global__ void __launch_bounds__(NTHREADS, 1) gemm_kernel(
    const __grid_constant__ CUtensorMap tma_a,
    const __grid_constant__ CUtensorMap tma_b,
    float* __restrict__ out)
{
    extern __shared__ char smem[];
    const uint32_t sb = smem_to_u32(smem);
    const int tid = threadIdx.x;
    const int wid = tid >> 5;
    const int lane = tid & 31;

    // Grouped tile order for L2 reuse. 64 M-tiles x 128 N-tiles.
    // group = 8 M-tiles x all N-tiles, n-major within group.
    const int bid = blockIdx.x;
    const int group = bid >> 10;                  // /(8*128)
    const int r = bid & 1023;
    const int bm = (group << 3) + (r & 7);
    const int bn = r >> 3;
    const int m0 = bm * BM;
    const int n0 = bn * BN;

    if (tid == 0) {
        #pragma unroll
        for (int s = 0; s < STAGES; s++) {
            MBARRIER_INIT(sb + SM_BAR + s * 16, 1);                 // full[s]: TMA tx
            MBARRIER_INIT(sb + SM_BAR + s * 16 + 8, NWARPS_COMPUTE); // empty[s]: 1/warp
        }
    }
    __syncthreads();

    if (wid == NWARPS_COMPUTE) {
        // ------------------------- TMA producer -------------------------
        if (elect_one_pred()) {
            int s = 0, phase = 1;   // fresh empty barriers: first STAGES waits pass
            for (int it = 0; it < K_ITERS; ++it) {
                MBARRIER_WAIT_PARITY_RELAXED(sb + SM_BAR + s * 16 + 8, phase);
                MBARRIER_EXPECT_TX(sb + SM_BAR + s * 16, A_BYTES + B_BYTES);
                TMA_LOAD_3D(sb + SM_A + s * A_BYTES, &tma_a, it * BK, m0, 0, sb + SM_BAR + s * 16);
                TMA_LOAD_3D(sb + SM_B + s * B_BYTES, &tma_b, it * BK, n0, 0, sb + SM_BAR + s * 16);
                if (++s == STAGES) { s = 0; phase ^= 1; }
            }
        }
        return;
    }

    // --------------------------- compute warps ---------------------------
    const int warp_m = wid >> 2;                  // 0..1 -> 64 rows
    const int warp_n = wid & 3;                   // 0..3 -> 32 cols
    float acc[4][4][4];                           // [mi][nj][4]
    #pragma unroll
    for (int i = 0; i < 4; i++)
        #pragma unroll
        for (int j = 0; j < 4; j++)
            #pragma unroll
            for (int c = 0; c < 4; c++) acc[i][j][c] = 0.f;

    // Per-thread ldmatrix byte offsets within a stage tile (before swizzle):
    // A (16x16 tile mi, kstep ks): row = warp_m*64 + mi*16 + (lane&15), kb = (lane>>4)*16
    // B (x4 covers n16 group g, kstep ks): q = lane>>3,
    //   nrow = warp_n*32 + g*16 + (q>>1)*8 + (lane&7), kb = (q&1)*16
    const uint32_t a_row = warp_m * 64 + (lane & 15);
    const uint32_t a_kb  = (lane >> 4) * 16;
    const uint32_t q     = lane >> 3;
    const uint32_t b_row = warp_n * 32 + ((q >> 1) * 8) + (lane & 7);
    const uint32_t b_kb  = (q & 1) * 16;

    int s = 0, phase = 0;
    for (int it = 0; it < K_ITERS; ++it) {
        MBARRIER_WAIT_PARITY(sb + SM_BAR + s * 16, phase);
        const uint32_t aBase = sb + SM_A + s * A_BYTES;
        const uint32_t bBase = sb + SM_B + s * B_BYTES;

        #pragma unroll
        for (int ks = 0; ks < BK / 16; ++ks) {
            uint32_t a[4][4];
            #pragma unroll
            for (int mi = 0; mi < 4; ++mi) {
                uint32_t off = (a_row + mi * 16) * 128 + ks * 32 + a_kb;
                LDMATRIX_X4(a[mi][0], a[mi][1], a[mi][2], a[mi][3], aBase + swz128(off));
            }
            uint32_t b[2][4];
            #pragma unroll
            for (int g = 0; g < 2; ++g) {
                uint32_t off = (b_row + g * 16) * 128 + ks * 32 + b_kb;
                LDMATRIX_X4(b[g][0], b[g][1], b[g][2], b[g][3], bBase + swz128(off));
            }
            #pragma unroll
            for (int mi = 0; mi < 4; ++mi) {
                #pragma unroll
                for (int nj = 0; nj < 4; ++nj) {
                    uint32_t bf[2] = { b[nj >> 1][2 * (nj & 1)], b[nj >> 1][2 * (nj & 1) + 1] };
                    MMA_16816(acc[mi][nj], a[mi], bf);
                }
            }
        }
        __syncwarp();
        if (elect_one_pred()) MBARRIER_ARRIVE(sb + SM_BAR + s * 16 + 8);
        if (++s == STAGES) { s = 0; phase ^= 1; }
    }

    // ------------------------------ epilogue ------------------------------
    // c fragment: thread holds C[m = lane/4 (+8)][n = 2*(lane%4) (+1)]
    const int er = m0 + warp_m * 64 + (lane >> 2);
    const int ec = n0 + warp_n * 32 + 2 * (lane & 3);
    #pragma unroll
    for (int mi = 0; mi < 4; ++mi) {
        #pragma unroll
        for (int nj = 0; nj < 4; ++nj) {
            float* p0 = out + (size_t)(er + mi * 16) * N_TOT + ec + nj * 8;
            float* p1 = p0 + (size_t)8 * N_TOT;
            reinterpret_cast<float2*>(p0)[0] = make_float2(acc[mi][nj][0], acc[mi][nj][1]);
            reinterpret_cast<float2*>(p1)[0] = make_float2(acc[mi][nj][2], acc[mi][nj][3]);
        }
    }
}

// ============================================================================
// Host side
// ============================================================================
typedef CUresult (*EncodeTiledFn)(
    CUtensorMap*, CUtensorMapDataType, cuuint32_t, void*,
    const cuuint64_t*, const cuuint64_t*, const cuuint32_t*, const cuuint32_t*,
    CUtensorMapInterleave, CUtensorMapSwizzle, CUtensorMapL2promotion,
    CUtensorMapFloatOOBfill);

static void make_tmap_f16_3d(EncodeTiledFn enc, CUtensorMap* tm, void* base,
                             uint64_t rows, uint32_t box_rows) {
    cuuint64_t dims[3]    = {(cuuint64_t)K_TOT, (cuuint64_t)rows, 1};
    cuuint64_t strides[2] = {(cuuint64_t)K_TOT * 2, (cuuint64_t)K_TOT * rows * 2};
    cuuint32_t box[3]     = {(cuuint32_t)BK, (cuuint32_t)box_rows, 1};
    cuuint32_t estr[3]    = {1, 1, 1};
    enc(tm, CU_TENSOR_MAP_DATA_TYPE_FLOAT16, 3, base, dims, strides, box, estr,
        CU_TENSOR_MAP_INTERLEAVE_NONE, CU_TENSOR_MAP_SWIZZLE_128B,
        CU_TENSOR_MAP_L2_PROMOTION_L2_128B, CU_TENSOR_MAP_FLOAT_OOB_FILL_NONE);
}

extern "C" void kernel_launch(void* const* d_in, const int* in_sizes, int n_in,
                              void* d_out, int out_size) {
    const float* x = (const float*)d_in[0];
    const float* w = (const float*)d_in[1];
    if (n_in >= 2 && in_sizes[0] == N_TOT * K_TOT) {  // weight first
        w = (const float*)d_in[0];
        x = (const float*)d_in[1];
    }
    float* out = (float*)d_out;

    void* xq_ptr = nullptr;
    void* wq_ptr = nullptr;
    cudaGetSymbolAddress(&xq_ptr, g_xq);
    cudaGetSymbolAddress(&wq_ptr, g_wq);

    EncodeTiledFn enc = nullptr;
    {
        void* p = nullptr;
        cudaDriverEntryPointQueryResult st;
#if CUDART_VERSION >= 12050
        cudaGetDriverEntryPointByVersion("cuTensorMapEncodeTiled", &p, 12000,
                                         cudaEnableDefault, &st);
#else
        cudaGetDriverEntryPoint("cuTensorMapEncodeTiled", &p, cudaEnableDefault, &st);
#endif
        enc = (EncodeTiledFn)p;
    }

    CUtensorMap tma_a, tma_b;
    make_tmap_f16_3d(enc, &tma_a, xq_ptr, M_TOT, BM);   // A: [K,M] K-major, box [64,128]
    make_tmap_f16_3d(enc, &tma_b, wq_ptr, N_TOT, BN);   // B: [K,N] K-major, box [64,128]

    absmean_partial_kernel<<<1024, 256>>>((const float4*)w);
    absmean_final_kernel<<<1, 1024>>>();
    quantize_w_kernel<<<16384, 256>>>((const float4*)w, (uint2*)wq_ptr);
    quantize_x_kernel<<<8192, 256>>>((const float4*)x, (uint2*)xq_ptr);

    cudaFuncSetAttribute(gemm_kernel, cudaFuncAttributeMaxDynamicSharedMemorySize, SMEM_TOTAL);
    const int grid = (M_TOT / BM) * (N_TOT / BN);   // 64 * 128 = 8192
    gemm_kernel<<<grid, NTHREADS, SMEM_TOTAL>>>(tma_a, tma_b, out);
    (void)out_size; (void)n_in;
}